// round 12
// baseline (speedup 1.0000x reference)
#include <cuda_runtime.h>

#define Hn   512
#define Tn   128
#define Bn   64
#define NROW 128
#define G4   2048
#define KE   1024
#define NTOK 8192

typedef unsigned long long ull;

// ---------------- static device scratch ----------------
__device__ __align__(16) float g_temb[(size_t)NTOK * KE];      // [tok][1024]
__device__ __align__(16) float g_WtT [(size_t)G4 * KE];        // [p][j]  (row-major over k!)
__device__ __align__(16) float g_Whh2[(size_t)Hn * G4];        // [jp][u*8 + g*2 + par]
__device__ __align__(16) float g_G   [(size_t)Tn * NROW * G4]; // [t'][orig_r][p]
__device__ __align__(16) float g_Msp [2][8][G4];
__device__ __align__(16) float g_cst [2][G4];
__device__ __align__(16) float g_h   [2][NROW * Hn];           // sorted row order
__device__ __align__(16) float g_hfin[NROW * Hn];              // sorted row order
__device__ int g_sortidx[Bn];   // sorted pos -> orig batch (desc by length)
__device__ int g_inv[Bn];       // orig batch -> sorted pos
__device__ int g_maxlen;
__device__ int          g_ctr;
__device__ volatile int g_rel;

// ---------------- helpers ----------------
__device__ __forceinline__ void fma2(ull& d, ull a, ull b) {
    asm("fma.rn.f32x2 %0, %1, %2, %0;" : "+l"(d) : "l"(a), "l"(b));
}
__device__ __forceinline__ float sum2(ull v) {
    float a, b;
    asm("mov.b64 {%0,%1}, %2;" : "=f"(a), "=f"(b) : "l"(v));
    return a + b;
}
__device__ __forceinline__ float sigf(float v) {
    return __fdividef(1.0f, 1.0f + __expf(-v));
}
__device__ __forceinline__ float tanhfast(float v) {
    float e = __expf(2.0f * v);
    return 1.0f - __fdividef(2.0f, e + 1.0f);
}
__device__ __forceinline__ void cpa16(const float* dst_s, const float* src_g) {
    unsigned s = (unsigned)__cvta_generic_to_shared(dst_s);
    asm volatile("cp.async.cg.shared.global [%0], [%1], 16;" :: "r"(s), "l"(src_g));
}
#define CP_COMMIT() asm volatile("cp.async.commit_group;" ::: "memory")
#define CP_WAIT0()  asm volatile("cp.async.wait_group 0;"  ::: "memory")

// ---------------- timestep embeddings (skip dead tokens) ----------------
__global__ void k_temb(const float* __restrict__ x, const int* __restrict__ lengths) {
    int tok = blockIdx.x;
    int b = tok >> 7, t = tok & 127;
    int cl = (__ldg(&lengths[b]) + 1) >> 1;
    if ((t & 63) >= cl) return;          // never consumed by the recurrence
    int k = threadIdx.x;                 // 256
    float t0 = x[tok * 16 + 0], t1 = x[tok * 16 + 1];
    float fr = __expf(-9.210340371976184f * (float)k * (1.0f / 256.0f));
    float s0, c0v, s1, c1v;
    __sincosf(t0 * fr, &s0, &c0v);
    __sincosf(t1 * fr, &s1, &c1v);
    float* o = g_temb + (size_t)tok * KE;
    o[k]       = c0v;
    o[k + 256] = s0;
    o[k + 512] = c1v;
    o[k + 768] = s1;
}

// ---------------- prep: W_ih[:,512:] -> [p][k] row-major ----------------
__global__ void k_wtT(const float* __restrict__ Wih) {
    int i = blockIdx.x * blockDim.x + threadIdx.x;     // 2097152 exact
    int p = i >> 10, j = i & 1023;
    int u = p >> 2, g = p & 3;
    g_WtT[i] = Wih[(size_t)(g * Hn + u) * 1536 + 512 + j];
}

// ---------------- prep: fold segment linears through W_ih ----------------
__global__ void k_fold(const float* __restrict__ Wih,
                       const float* __restrict__ Wis0, const float* __restrict__ bis0,
                       const float* __restrict__ Wis1, const float* __restrict__ bis1,
                       const float* __restrict__ bih,  const float* __restrict__ bhh) {
    int idx = blockIdx.x * blockDim.x + threadIdx.x;   // 32768 = 2048 p * 16 items
    int p = idx >> 4, item = idx & 15;
    int u = p >> 2, g = p & 3;
    const float* wr = Wih + (size_t)(g * Hn + u) * 1536;
    float acc = 0.0f;
    if (item < 8) {
        for (int k = 0; k < Hn; k++) acc += wr[k] * Wis0[k * 8 + item];
        g_Msp[0][item][p] = acc;
    } else if (item < 14) {
        int m = item - 8;
        for (int k = 0; k < Hn; k++) acc += wr[k] * Wis1[k * 6 + m];
        g_Msp[1][m][p] = acc;
    } else if (item == 14) {
        for (int k = 0; k < Hn; k++) acc += wr[k] * bis0[k];
        g_cst[0][p] = acc + bih[g * Hn + u] + bhh[g * Hn + u];
    } else {
        for (int k = 0; k < Hn; k++) acc += wr[k] * bis1[k];
        g_cst[1][p] = acc + bih[g * Hn + u] + bhh[g * Hn + u];
    }
}

// ---------------- big GEMM: cp.async double-buffered + dead-row skip ----------------
// C[tok][p] = temb[tok][:] . WtT[p][:]; BM=128 (tokens of one b) x BN=64 x BK=32.
// smem rows padded to 36 floats; (k,k+1) adjacent -> natural f32x2 operands.
#define AS_ELT (128 * 36)
#define BS_ELT (64 * 36)
#define GEMM_SMEM ((2 * AS_ELT + 2 * BS_ELT) * 4)

__global__ void __launch_bounds__(256) k_gemm(const float* __restrict__ x,
                                              const int* __restrict__ lengths) {
    extern __shared__ float sm[];
    float* As = sm;                    // [2][128][36]
    float* Bs = sm + 2 * AS_ELT;       // [2][64][36]
    int b  = blockIdx.y;
    int pt = blockIdx.x * 64;
    int tid = threadIdx.x;
    int tx = tid & 15, ty = tid >> 4;
    int m0 = ty * 8, n0 = tx * 4;
    int blen = __ldg(&lengths[b]);
    int cl = (blen + 1) >> 1;
    bool alive = ((m0 & 63) < cl);

    ull acc[8][4];
    #pragma unroll
    for (int i = 0; i < 8; i++)
        #pragma unroll
        for (int j = 0; j < 4; j++) acc[i][j] = 0ull;

    const float* Abase = g_temb + (size_t)b * 128 * KE;
    const float* Bbase = g_WtT + (size_t)pt * KE;

    // prologue: load chunk 0 into buffer 0
    {
        #pragma unroll
        for (int it = 0; it < 4; it++) {
            int e = tid + it * 256;                // 1024 chunks of 16B
            int m = e >> 3, kk = (e & 7) * 4;
            if ((m & 63) < cl)
                cpa16(As + m * 36 + kk, Abase + (size_t)m * KE + kk);
        }
        #pragma unroll
        for (int it = 0; it < 2; it++) {
            int e = tid + it * 256;                // 512 chunks
            int n = e >> 3, kk = (e & 7) * 4;
            cpa16(Bs + n * 36 + kk, Bbase + (size_t)n * KE + kk);
        }
        CP_COMMIT();
        CP_WAIT0();
        __syncthreads();
    }

    for (int k0 = 0; k0 < KE; k0 += 32) {
        int cur = (k0 >> 5) & 1;
        int nxt = cur ^ 1;
        if (k0 + 32 < KE) {
            float* Ab = As + nxt * AS_ELT;
            float* Bb = Bs + nxt * BS_ELT;
            #pragma unroll
            for (int it = 0; it < 4; it++) {
                int e = tid + it * 256;
                int m = e >> 3, kk = (e & 7) * 4;
                if ((m & 63) < cl)
                    cpa16(Ab + m * 36 + kk, Abase + (size_t)m * KE + k0 + 32 + kk);
            }
            #pragma unroll
            for (int it = 0; it < 2; it++) {
                int e = tid + it * 256;
                int n = e >> 3, kk = (e & 7) * 4;
                cpa16(Bb + n * 36 + kk, Bbase + (size_t)n * KE + k0 + 32 + kk);
            }
            CP_COMMIT();
        }

        if (alive) {
            const float* Ab = As + cur * AS_ELT + m0 * 36;
            const float* Bb = Bs + cur * BS_ELT + n0 * 36;
            #pragma unroll
            for (int kp2 = 0; kp2 < 8; kp2++) {
                ulonglong2 a2[8], b2[4];
                #pragma unroll
                for (int i = 0; i < 8; i++)
                    a2[i] = *(const ulonglong2*)(Ab + i * 36 + kp2 * 4);
                #pragma unroll
                for (int j = 0; j < 4; j++)
                    b2[j] = *(const ulonglong2*)(Bb + j * 36 + kp2 * 4);
                #pragma unroll
                for (int i = 0; i < 8; i++)
                    #pragma unroll
                    for (int j = 0; j < 4; j++) {
                        fma2(acc[i][j], a2[i].x, b2[j].x);
                        fma2(acc[i][j], a2[i].y, b2[j].y);
                    }
            }
        }

        if (k0 + 32 < KE) CP_WAIT0();
        __syncthreads();
    }

    // epilogue: add folded segment contribution, route per the concat/reshape quirk
    #pragma unroll
    for (int i = 0; i < 8; i++) {
        int t = m0 + i;
        const float* xr = x + ((size_t)b * 128 + t) * 16;
        float cval[4];
        #pragma unroll
        for (int j = 0; j < 4; j++) cval[j] = sum2(acc[i][j]);
        #pragma unroll
        for (int se = 0; se < 2; se++) {
            int L = t * 2 + se;
            int sp = L >> 7, tp = L & 127;
            if (tp >= blen) continue;          // never read by the recurrence
            float4 outv;
            float* ov = &outv.x;
            int p = pt + n0;
            #pragma unroll
            for (int j = 0; j < 4; j++) {
                float v = cval[j] + g_cst[se][p + j];
                if (se == 0) {
                    #pragma unroll
                    for (int m = 0; m < 8; m++) v += xr[2 + m] * g_Msp[0][m][p + j];
                } else {
                    #pragma unroll
                    for (int m = 0; m < 6; m++) v += xr[10 + m] * g_Msp[1][m][p + j];
                }
                ov[j] = v;
            }
            *(float4*)&g_G[((size_t)tp * NROW + (b * 2 + sp)) * G4 + p] = outv;
        }
    }
}

// ---------------- sort batches by length (desc), single thread ----------------
__global__ void k_sort(const int* __restrict__ lengths) {
    if (threadIdx.x == 0 && blockIdx.x == 0) {
        int idx[Bn], len[Bn];
        for (int i = 0; i < Bn; i++) { idx[i] = i; len[i] = lengths[i]; }
        for (int a = 0; a < Bn - 1; a++) {
            int m = a;
            for (int b2 = a + 1; b2 < Bn; b2++) if (len[b2] > len[m]) m = b2;
            int tl = len[a]; len[a] = len[m]; len[m] = tl;
            int ti = idx[a]; idx[a] = idx[m]; idx[m] = ti;
        }
        for (int i = 0; i < Bn; i++) { g_sortidx[i] = idx[i]; g_inv[idx[i]] = i; }
        g_maxlen = len[0];
    }
}

// ---------------- prep: permuted W_hh copy ----------------
__global__ void k_whh2(const float* __restrict__ Whh) {
    int i = blockIdx.x * blockDim.x + threadIdx.x;     // 1048576 exact
    int jp = i >> 12, rem = i & 4095;
    int u = rem >> 3, g = (rem >> 1) & 3, par = i & 1;
    g_Whh2[i] = Whh[(size_t)(g * Hn + u) * Hn + 2 * jp + par];
}

// ---------------- init h (sorted row order) + barrier reset ----------------
__global__ void k_inith(const float* __restrict__ h0) {
    int i = blockIdx.x * blockDim.x + threadIdx.x;     // 65536 exact
    int rs = i >> 9, u = i & 511;
    g_h[0][i] = h0[g_sortidx[rs >> 1] * Hn + u];
    if (i == 0) { g_ctr = 0; g_rel = 0; }
}

// ---------------- persistent recurrence kernel ----------------
#define HS_STRIDE 516
#define RED_OFF   (32 * HS_STRIDE)
#define RNN_SMEM  ((RED_OFF + 128 * 16) * 4)

__global__ void __launch_bounds__(256, 1) k_rnn(const int* __restrict__ lengths,
                                                const float* __restrict__ c0) {
    extern __shared__ float hs[];            // [32 rows][516] + red[128][16]
    float* red = hs + RED_OFF;
    int tid    = threadIdx.x;
    int uidx   = tid & 15;
    int rslot  = (tid >> 4) & 7;             // 0..7
    int jhalf  = tid >> 7;                   // 0/1
    int unit   = blockIdx.x * 16 + uidx;
    int rowbase = blockIdx.y * 32;
    int r0 = rowbase + rslot * 4;            // sorted row
    int jp0 = jhalf * 128;

    float c[4];
    int   mylen[4];
    const float* gbase[4];
    #pragma unroll
    for (int i = 0; i < 4; i++) {
        int sr = r0 + i;
        int ob = g_sortidx[sr >> 1];                       // original batch
        c[i]     = __ldg(&c0[ob * Hn + unit]);
        mylen[i] = __ldg(&lengths[ob]);
        gbase[i] = g_G + (size_t)(ob * 2 + (sr & 1)) * G4 + unit * 4;
    }
    int groupmax = __ldg(&lengths[g_sortidx[rowbase >> 1]]);  // first = largest in group
    int tmax = g_maxlen;

    const float* wbase = g_Whh2 + unit * 8;

    for (int t = 0; t < tmax; t++) {
        if (t < groupmax) {
            const float* hin  = g_h[t & 1];
            float*       hout = g_h[(t + 1) & 1];

            // stage 32-row h tile (4096 float4s); bypass L1
            #pragma unroll
            for (int e = tid; e < 4096; e += 256) {
                int rl = e >> 7, u4 = (e & 127) << 2;
                float4 v = __ldcg((const float4*)(hin + (size_t)(rowbase + rl) * Hn + u4));
                *(float4*)&hs[rl * HS_STRIDE + u4] = v;
            }
            __syncthreads();

            float4 gin[4];
            if (jhalf == 0) {
                #pragma unroll
                for (int i = 0; i < 4; i++)
                    gin[i] = __ldcg((const float4*)(gbase[i] + (size_t)t * NROW * G4));
            }

            ull acc[4][4];
            #pragma unroll
            for (int i = 0; i < 4; i++)
                #pragma unroll
                for (int g = 0; g < 4; g++) acc[i][g] = 0ull;

            const float* hp = hs + (size_t)(rslot * 4) * HS_STRIDE;
            #pragma unroll 4
            for (int jp = jp0; jp < jp0 + 128; jp++) {
                ulonglong2 wA = *(const ulonglong2*)(wbase + (size_t)jp * 4096);
                ulonglong2 wB = *(const ulonglong2*)(wbase + (size_t)jp * 4096 + 4);
                ull h0 = *(const ull*)(hp + 0 * HS_STRIDE + jp * 2);
                ull h1 = *(const ull*)(hp + 1 * HS_STRIDE + jp * 2);
                ull h2 = *(const ull*)(hp + 2 * HS_STRIDE + jp * 2);
                ull h3 = *(const ull*)(hp + 3 * HS_STRIDE + jp * 2);
                fma2(acc[0][0], h0, wA.x); fma2(acc[0][1], h0, wA.y);
                fma2(acc[0][2], h0, wB.x); fma2(acc[0][3], h0, wB.y);
                fma2(acc[1][0], h1, wA.x); fma2(acc[1][1], h1, wA.y);
                fma2(acc[1][2], h1, wB.x); fma2(acc[1][3], h1, wB.y);
                fma2(acc[2][0], h2, wA.x); fma2(acc[2][1], h2, wA.y);
                fma2(acc[2][2], h2, wB.x); fma2(acc[2][3], h2, wB.y);
                fma2(acc[3][0], h3, wA.x); fma2(acc[3][1], h3, wA.y);
                fma2(acc[3][2], h3, wB.x); fma2(acc[3][3], h3, wB.y);
            }

            if (jhalf == 1) {
                float* rp = red + (rslot * 16 + uidx) * 16;
                #pragma unroll
                for (int i = 0; i < 4; i++)
                    #pragma unroll
                    for (int g = 0; g < 4; g++) rp[i * 4 + g] = sum2(acc[i][g]);
            }
            __syncthreads();

            if (jhalf == 0) {
                const float* rp = red + (rslot * 16 + uidx) * 16;
                #pragma unroll
                for (int i = 0; i < 4; i++) {
                    int r = r0 + i;
                    float iv = sum2(acc[i][0]) + rp[i * 4 + 0] + gin[i].x;
                    float fv = sum2(acc[i][1]) + rp[i * 4 + 1] + gin[i].y;
                    float gv = sum2(acc[i][2]) + rp[i * 4 + 2] + gin[i].z;
                    float ov = sum2(acc[i][3]) + rp[i * 4 + 3] + gin[i].w;
                    float ig = sigf(iv), fg = sigf(fv), og = sigf(ov);
                    float gg = tanhfast(gv);
                    c[i] = fg * c[i] + ig * gg;
                    float h = og * tanhfast(c[i]);
                    __stcg(&hout[(size_t)r * Hn + unit], h);
                    if (t + 1 == mylen[i]) g_hfin[(size_t)r * Hn + unit] = h;
                }
            }
            __syncthreads();
        }

        // device-wide barrier (128 co-resident blocks; monotonic counter)
        if (tid == 0) {
            __threadfence();
            int old = atomicAdd(&g_ctr, 1);
            if (old == (t + 1) * 128 - 1) {
                g_rel = t + 1;
            } else {
                while (g_rel < t + 1) { }
            }
        }
        __syncthreads();
    }
}

// ---------------- output head ----------------
__global__ void k_out(const float* __restrict__ Wo, const float* __restrict__ bo,
                      float* __restrict__ out) {
    __shared__ float red[14][129];
    int b = blockIdx.x, tid = threadIdx.x;   // 128 threads
    int pos = g_inv[b];
    float acc[14];
    #pragma unroll
    for (int o = 0; o < 14; o++) acc[o] = 0.0f;
    for (int q = tid; q < 1024; q += 128) {
        int row = pos * 2 + (q >> 9);
        float hv = g_hfin[row * Hn + (q & 511)];
        #pragma unroll
        for (int o = 0; o < 14; o++) acc[o] += hv * Wo[o * 1024 + q];
    }
    #pragma unroll
    for (int o = 0; o < 14; o++) red[o][tid] = acc[o];
    __syncthreads();
    if (tid < 14) {
        float s = bo[tid];
        for (int k = 0; k < 128; k++) s += red[tid][k];
        out[b * 14 + tid] = sigf(s);
    }
}

// ---------------- launch ----------------
extern "C" void kernel_launch(void* const* d_in, const int* in_sizes, int n_in,
                              void* d_out, int out_size) {
    const float* x    = (const float*)d_in[0];
    const int*   len  = (const int*)  d_in[1];
    const float* h0   = (const float*)d_in[2];
    const float* c0   = (const float*)d_in[3];
    const float* Wis0 = (const float*)d_in[4];
    const float* bis0 = (const float*)d_in[5];
    const float* Wis1 = (const float*)d_in[6];
    const float* bis1 = (const float*)d_in[7];
    const float* Wih  = (const float*)d_in[8];
    const float* Whh  = (const float*)d_in[9];
    const float* bih  = (const float*)d_in[10];
    const float* bhh  = (const float*)d_in[11];
    const float* Wo   = (const float*)d_in[12];
    const float* bo   = (const float*)d_in[13];
    float* out = (float*)d_out;

    cudaFuncSetAttribute(k_rnn,  cudaFuncAttributeMaxDynamicSharedMemorySize, RNN_SMEM);
    cudaFuncSetAttribute(k_gemm, cudaFuncAttributeMaxDynamicSharedMemorySize, GEMM_SMEM);

    k_temb <<<8192, 256>>>(x, len);                              // 1
    k_wtT  <<<8192, 256>>>(Wih);                                 // 2
    k_fold <<<128, 256>>>(Wih, Wis0, bis0, Wis1, bis1, bih, bhh);// 3
    k_gemm <<<dim3(32, 64), 256, GEMM_SMEM>>>(x, len);           // 4  <- profiled slot
    k_sort <<<1, 32>>>(len);                                     // 5
    k_whh2 <<<4096, 256>>>(Whh);                                 // 6
    k_inith<<<256, 256>>>(h0);                                   // 7
    k_rnn  <<<dim3(32, 4), 256, RNN_SMEM>>>(len, c0);            // 8
    k_out  <<<64, 128>>>(Wo, bo, out);                           // 9
}

// round 13
// speedup vs baseline: 1.2106x; 1.2106x over previous
#include <cuda_runtime.h>

#define Hn   512
#define Tn   128
#define Bn   64
#define NROW 128
#define G4   2048
#define KE   1024
#define NTOK 8192

typedef unsigned long long ull;

// ---------------- static device scratch ----------------
__device__ __align__(16) float g_temb[(size_t)NTOK * KE];      // [tok][1024]
// W_ih tail, pre-swizzled: [ptile(32)][kchunk(32)][kp(16)][j(4)][tx(16)] ulls (f32x2 pairs)
__device__ __align__(16) float g_WtT [(size_t)G4 * KE];
__device__ __align__(16) float g_Whh2[(size_t)Hn * G4];        // [jp][u*8 + g*2 + par]
__device__ __align__(16) float g_G   [(size_t)Tn * NROW * G4]; // [t'][orig_r][p]
__device__ __align__(16) float g_Msp [2][8][G4];
__device__ __align__(16) float g_cst [2][G4];
__device__ __align__(16) float g_h   [2][NROW * Hn];           // sorted row order
__device__ __align__(16) float g_hfin[NROW * Hn];              // sorted row order
__device__ int g_sortidx[Bn];   // sorted pos -> orig batch (desc by length)
__device__ int g_inv[Bn];       // orig batch -> sorted pos
__device__ int g_maxlen;
__device__ int          g_ctr;
__device__ volatile int g_rel;

// ---------------- helpers ----------------
__device__ __forceinline__ void fma2(ull& d, ull a, ull b) {
    asm("fma.rn.f32x2 %0, %1, %2, %0;" : "+l"(d) : "l"(a), "l"(b));
}
__device__ __forceinline__ float sum2(ull v) {
    float a, b;
    asm("mov.b64 {%0,%1}, %2;" : "=f"(a), "=f"(b) : "l"(v));
    return a + b;
}
__device__ __forceinline__ float sigf(float v) {
    return __fdividef(1.0f, 1.0f + __expf(-v));
}
__device__ __forceinline__ float tanhfast(float v) {
    float e = __expf(2.0f * v);
    return 1.0f - __fdividef(2.0f, e + 1.0f);
}
__device__ __forceinline__ void cpa16(const float* dst_s, const float* src_g) {
    unsigned s = (unsigned)__cvta_generic_to_shared(dst_s);
    asm volatile("cp.async.cg.shared.global [%0], [%1], 16;" :: "r"(s), "l"(src_g));
}
#define CP_COMMIT() asm volatile("cp.async.commit_group;" ::: "memory")
#define CP_WAIT0()  asm volatile("cp.async.wait_group 0;"  ::: "memory")

// ---------------- timestep embeddings (skip dead tokens) ----------------
__global__ void k_temb(const float* __restrict__ x, const int* __restrict__ lengths) {
    int tok = blockIdx.x;
    int b = tok >> 7, t = tok & 127;
    int cl = (__ldg(&lengths[b]) + 1) >> 1;
    if ((t & 63) >= cl) return;          // never consumed by the recurrence
    int k = threadIdx.x;                 // 256
    float t0 = x[tok * 16 + 0], t1 = x[tok * 16 + 1];
    float fr = __expf(-9.210340371976184f * (float)k * (1.0f / 256.0f));
    float s0, c0v, s1, c1v;
    __sincosf(t0 * fr, &s0, &c0v);
    __sincosf(t1 * fr, &s1, &c1v);
    float* o = g_temb + (size_t)tok * KE;
    o[k]       = c0v;
    o[k + 256] = s0;
    o[k + 512] = c1v;
    o[k + 768] = s1;
}

// ---------------- prep: W_ih[:,512:] -> swizzled [ptile][kchunk][kp][j][tx] f32x2 ----------------
__global__ void k_wtT(const float* __restrict__ Wih) {
    int i = blockIdx.x * blockDim.x + threadIdx.x;     // 2097152 exact
    int par    = i & 1;
    int txi    = (i >> 1) & 15;
    int j      = (i >> 5) & 3;
    int kpl    = (i >> 7) & 15;
    int kchunk = (i >> 11) & 31;
    int ptile  = i >> 16;
    int p = ptile * 64 + txi * 4 + j;
    int k = kchunk * 32 + kpl * 2 + par;
    int u = p >> 2, g = p & 3;
    g_WtT[i] = Wih[(size_t)(g * Hn + u) * 1536 + 512 + k];
}

// ---------------- prep: fold segment linears through W_ih ----------------
__global__ void k_fold(const float* __restrict__ Wih,
                       const float* __restrict__ Wis0, const float* __restrict__ bis0,
                       const float* __restrict__ Wis1, const float* __restrict__ bis1,
                       const float* __restrict__ bih,  const float* __restrict__ bhh) {
    int idx = blockIdx.x * blockDim.x + threadIdx.x;   // 32768 = 2048 p * 16 items
    int p = idx >> 4, item = idx & 15;
    int u = p >> 2, g = p & 3;
    const float* wr = Wih + (size_t)(g * Hn + u) * 1536;
    float acc = 0.0f;
    if (item < 8) {
        for (int k = 0; k < Hn; k++) acc += wr[k] * Wis0[k * 8 + item];
        g_Msp[0][item][p] = acc;
    } else if (item < 14) {
        int m = item - 8;
        for (int k = 0; k < Hn; k++) acc += wr[k] * Wis1[k * 6 + m];
        g_Msp[1][m][p] = acc;
    } else if (item == 14) {
        for (int k = 0; k < Hn; k++) acc += wr[k] * bis0[k];
        g_cst[0][p] = acc + bih[g * Hn + u] + bhh[g * Hn + u];
    } else {
        for (int k = 0; k < Hn; k++) acc += wr[k] * bis1[k];
        g_cst[1][p] = acc + bih[g * Hn + u] + bhh[g * Hn + u];
    }
}

// ---------------- big GEMM: conflict-free smem + cp.async + 2 blocks/SM ----------------
// C[tok][p] = temb[tok][:] . W[p][:]; BM=128 (tokens of one b) x BN=64 x BK=32.
// A smem: [2][128][18] ulls (f32x2 over k, stride 18 -> 16B aligned rows).
// B smem: [2][16 kp][4 j][16 tx] ulls -> LDS.64 hits all 32 banks once.
#define AS_ULL (128 * 18)
#define BS_ULL (16 * 4 * 16)
#define GEMM_SMEM ((2 * AS_ULL + 2 * BS_ULL) * 8)

__global__ void __launch_bounds__(256, 2) k_gemm(const float* __restrict__ x,
                                                 const int* __restrict__ lengths) {
    extern __shared__ ull smu[];
    ull* As = smu;                  // [2][128][18]
    ull* Bs = smu + 2 * AS_ULL;     // [2][1024]
    int b     = blockIdx.y;
    int ptile = blockIdx.x;
    int pt    = ptile * 64;
    int tid = threadIdx.x;
    int tx = tid & 15, ty = tid >> 4;
    int m0 = ty * 8, n0 = tx * 4;
    int blen = __ldg(&lengths[b]);
    int cl = (blen + 1) >> 1;
    bool alive = ((m0 & 63) < cl);

    ull acc[8][4];
    #pragma unroll
    for (int i = 0; i < 8; i++)
        #pragma unroll
        for (int j = 0; j < 4; j++) acc[i][j] = 0ull;

    const float* Abase = g_temb + (size_t)b * 128 * KE;
    const float* Bbase = g_WtT + ((size_t)ptile << 16);   // 32 chunks * 2048 floats

    // prologue: chunk 0 -> buffer 0
    {
        float* Ad = (float*)As;
        float* Bd = (float*)Bs;
        #pragma unroll
        for (int it = 0; it < 4; it++) {
            int e = tid + it * 256;                 // 1024 x 16B
            int m = e >> 3, q8 = e & 7;
            if ((m & 63) < cl)
                cpa16(Ad + (m * 18 + q8 * 2) * 2, Abase + (size_t)m * KE + q8 * 4);
        }
        #pragma unroll
        for (int it = 0; it < 2; it++) {
            int e = tid + it * 256;                 // 512 x 16B
            cpa16(Bd + e * 4, Bbase + e * 4);
        }
        CP_COMMIT();
        CP_WAIT0();
        __syncthreads();
    }

    for (int kc = 0; kc < 32; kc++) {
        int cur = kc & 1, nxt = cur ^ 1;
        if (kc + 1 < 32) {
            float* Ad = (float*)(As + nxt * AS_ULL);
            float* Bd = (float*)(Bs + nxt * BS_ULL);
            int k0n = (kc + 1) * 32;
            #pragma unroll
            for (int it = 0; it < 4; it++) {
                int e = tid + it * 256;
                int m = e >> 3, q8 = e & 7;
                if ((m & 63) < cl)
                    cpa16(Ad + (m * 18 + q8 * 2) * 2, Abase + (size_t)m * KE + k0n + q8 * 4);
            }
            #pragma unroll
            for (int it = 0; it < 2; it++) {
                int e = tid + it * 256;
                cpa16(Bd + e * 4, Bbase + (kc + 1) * 2048 + e * 4);
            }
            CP_COMMIT();
        }

        if (alive) {
            const ull* Ab = As + cur * AS_ULL + m0 * 18;
            const ull* Bb = Bs + cur * BS_ULL;
            #pragma unroll
            for (int q = 0; q < 8; q++) {
                ulonglong2 av[8];
                #pragma unroll
                for (int i = 0; i < 8; i++)
                    av[i] = *(const ulonglong2*)(Ab + i * 18 + 2 * q);
                ull b0[4], b1[4];
                #pragma unroll
                for (int j = 0; j < 4; j++) {
                    b0[j] = Bb[(2 * q)     * 64 + j * 16 + tx];
                    b1[j] = Bb[(2 * q + 1) * 64 + j * 16 + tx];
                }
                #pragma unroll
                for (int i = 0; i < 8; i++)
                    #pragma unroll
                    for (int j = 0; j < 4; j++) {
                        fma2(acc[i][j], av[i].x, b0[j]);
                        fma2(acc[i][j], av[i].y, b1[j]);
                    }
            }
        }

        if (kc + 1 < 32) CP_WAIT0();
        __syncthreads();
    }

    // epilogue: add folded segment contribution, route per the concat/reshape quirk
    #pragma unroll
    for (int i = 0; i < 8; i++) {
        int t = m0 + i;
        const float* xr = x + ((size_t)b * 128 + t) * 16;
        float cval[4];
        #pragma unroll
        for (int j = 0; j < 4; j++) cval[j] = sum2(acc[i][j]);
        #pragma unroll
        for (int se = 0; se < 2; se++) {
            int L = t * 2 + se;
            int sp = L >> 7, tp = L & 127;
            if (tp >= blen) continue;          // never read by the recurrence
            float4 outv;
            float* ov = &outv.x;
            int p = pt + n0;
            #pragma unroll
            for (int j = 0; j < 4; j++) {
                float v = cval[j] + g_cst[se][p + j];
                if (se == 0) {
                    #pragma unroll
                    for (int m = 0; m < 8; m++) v += xr[2 + m] * g_Msp[0][m][p + j];
                } else {
                    #pragma unroll
                    for (int m = 0; m < 6; m++) v += xr[10 + m] * g_Msp[1][m][p + j];
                }
                ov[j] = v;
            }
            *(float4*)&g_G[((size_t)tp * NROW + (b * 2 + sp)) * G4 + p] = outv;
        }
    }
}

// ---------------- sort batches by length (desc), single thread ----------------
__global__ void k_sort(const int* __restrict__ lengths) {
    if (threadIdx.x == 0 && blockIdx.x == 0) {
        int idx[Bn], len[Bn];
        for (int i = 0; i < Bn; i++) { idx[i] = i; len[i] = lengths[i]; }
        for (int a = 0; a < Bn - 1; a++) {
            int m = a;
            for (int b2 = a + 1; b2 < Bn; b2++) if (len[b2] > len[m]) m = b2;
            int tl = len[a]; len[a] = len[m]; len[m] = tl;
            int ti = idx[a]; idx[a] = idx[m]; idx[m] = ti;
        }
        for (int i = 0; i < Bn; i++) { g_sortidx[i] = idx[i]; g_inv[idx[i]] = i; }
        g_maxlen = len[0];
    }
}

// ---------------- prep: permuted W_hh copy ----------------
__global__ void k_whh2(const float* __restrict__ Whh) {
    int i = blockIdx.x * blockDim.x + threadIdx.x;     // 1048576 exact
    int jp = i >> 12, rem = i & 4095;
    int u = rem >> 3, g = (rem >> 1) & 3, par = i & 1;
    g_Whh2[i] = Whh[(size_t)(g * Hn + u) * Hn + 2 * jp + par];
}

// ---------------- init h (sorted row order) + barrier reset ----------------
__global__ void k_inith(const float* __restrict__ h0) {
    int i = blockIdx.x * blockDim.x + threadIdx.x;     // 65536 exact
    int rs = i >> 9, u = i & 511;
    g_h[0][i] = h0[g_sortidx[rs >> 1] * Hn + u];
    if (i == 0) { g_ctr = 0; g_rel = 0; }
}

// ---------------- persistent recurrence kernel ----------------
#define HS_STRIDE 516
#define RED_OFF   (32 * HS_STRIDE)
#define RNN_SMEM  ((RED_OFF + 128 * 16) * 4)

__global__ void __launch_bounds__(256, 1) k_rnn(const int* __restrict__ lengths,
                                                const float* __restrict__ c0) {
    extern __shared__ float hs[];            // [32 rows][516] + red[128][16]
    float* red = hs + RED_OFF;
    int tid    = threadIdx.x;
    int uidx   = tid & 15;
    int rslot  = (tid >> 4) & 7;             // 0..7
    int jhalf  = tid >> 7;                   // 0/1
    int unit   = blockIdx.x * 16 + uidx;
    int rowbase = blockIdx.y * 32;
    int r0 = rowbase + rslot * 4;            // sorted row
    int jp0 = jhalf * 128;

    float c[4];
    int   mylen[4];
    const float* gbase[4];
    #pragma unroll
    for (int i = 0; i < 4; i++) {
        int sr = r0 + i;
        int ob = g_sortidx[sr >> 1];                       // original batch
        c[i]     = __ldg(&c0[ob * Hn + unit]);
        mylen[i] = __ldg(&lengths[ob]);
        gbase[i] = g_G + (size_t)(ob * 2 + (sr & 1)) * G4 + unit * 4;
    }
    int groupmax = __ldg(&lengths[g_sortidx[rowbase >> 1]]);  // first = largest in group
    int tmax = g_maxlen;

    const float* wbase = g_Whh2 + unit * 8;

    for (int t = 0; t < tmax; t++) {
        if (t < groupmax) {
            const float* hin  = g_h[t & 1];
            float*       hout = g_h[(t + 1) & 1];

            // stage 32-row h tile (4096 float4s); bypass L1
            #pragma unroll
            for (int e = tid; e < 4096; e += 256) {
                int rl = e >> 7, u4 = (e & 127) << 2;
                float4 v = __ldcg((const float4*)(hin + (size_t)(rowbase + rl) * Hn + u4));
                *(float4*)&hs[rl * HS_STRIDE + u4] = v;
            }
            __syncthreads();

            float4 gin[4];
            if (jhalf == 0) {
                #pragma unroll
                for (int i = 0; i < 4; i++)
                    gin[i] = __ldcg((const float4*)(gbase[i] + (size_t)t * NROW * G4));
            }

            ull acc[4][4];
            #pragma unroll
            for (int i = 0; i < 4; i++)
                #pragma unroll
                for (int g = 0; g < 4; g++) acc[i][g] = 0ull;

            const float* hp = hs + (size_t)(rslot * 4) * HS_STRIDE;
            #pragma unroll 4
            for (int jp = jp0; jp < jp0 + 128; jp++) {
                ulonglong2 wA = *(const ulonglong2*)(wbase + (size_t)jp * 4096);
                ulonglong2 wB = *(const ulonglong2*)(wbase + (size_t)jp * 4096 + 4);
                ull h0 = *(const ull*)(hp + 0 * HS_STRIDE + jp * 2);
                ull h1 = *(const ull*)(hp + 1 * HS_STRIDE + jp * 2);
                ull h2 = *(const ull*)(hp + 2 * HS_STRIDE + jp * 2);
                ull h3 = *(const ull*)(hp + 3 * HS_STRIDE + jp * 2);
                fma2(acc[0][0], h0, wA.x); fma2(acc[0][1], h0, wA.y);
                fma2(acc[0][2], h0, wB.x); fma2(acc[0][3], h0, wB.y);
                fma2(acc[1][0], h1, wA.x); fma2(acc[1][1], h1, wA.y);
                fma2(acc[1][2], h1, wB.x); fma2(acc[1][3], h1, wB.y);
                fma2(acc[2][0], h2, wA.x); fma2(acc[2][1], h2, wA.y);
                fma2(acc[2][2], h2, wB.x); fma2(acc[2][3], h2, wB.y);
                fma2(acc[3][0], h3, wA.x); fma2(acc[3][1], h3, wA.y);
                fma2(acc[3][2], h3, wB.x); fma2(acc[3][3], h3, wB.y);
            }

            if (jhalf == 1) {
                float* rp = red + (rslot * 16 + uidx) * 16;
                #pragma unroll
                for (int i = 0; i < 4; i++)
                    #pragma unroll
                    for (int g = 0; g < 4; g++) rp[i * 4 + g] = sum2(acc[i][g]);
            }
            __syncthreads();

            if (jhalf == 0) {
                const float* rp = red + (rslot * 16 + uidx) * 16;
                #pragma unroll
                for (int i = 0; i < 4; i++) {
                    int r = r0 + i;
                    float iv = sum2(acc[i][0]) + rp[i * 4 + 0] + gin[i].x;
                    float fv = sum2(acc[i][1]) + rp[i * 4 + 1] + gin[i].y;
                    float gv = sum2(acc[i][2]) + rp[i * 4 + 2] + gin[i].z;
                    float ov = sum2(acc[i][3]) + rp[i * 4 + 3] + gin[i].w;
                    float ig = sigf(iv), fg = sigf(fv), og = sigf(ov);
                    float gg = tanhfast(gv);
                    c[i] = fg * c[i] + ig * gg;
                    float h = og * tanhfast(c[i]);
                    __stcg(&hout[(size_t)r * Hn + unit], h);
                    if (t + 1 == mylen[i]) g_hfin[(size_t)r * Hn + unit] = h;
                }
            }
            __syncthreads();
        }

        // device-wide barrier (128 co-resident blocks; monotonic counter)
        if (tid == 0) {
            __threadfence();
            int old = atomicAdd(&g_ctr, 1);
            if (old == (t + 1) * 128 - 1) {
                g_rel = t + 1;
            } else {
                while (g_rel < t + 1) { }
            }
        }
        __syncthreads();
    }
}

// ---------------- output head ----------------
__global__ void k_out(const float* __restrict__ Wo, const float* __restrict__ bo,
                      float* __restrict__ out) {
    __shared__ float red[14][129];
    int b = blockIdx.x, tid = threadIdx.x;   // 128 threads
    int pos = g_inv[b];
    float acc[14];
    #pragma unroll
    for (int o = 0; o < 14; o++) acc[o] = 0.0f;
    for (int q = tid; q < 1024; q += 128) {
        int row = pos * 2 + (q >> 9);
        float hv = g_hfin[row * Hn + (q & 511)];
        #pragma unroll
        for (int o = 0; o < 14; o++) acc[o] += hv * Wo[o * 1024 + q];
    }
    #pragma unroll
    for (int o = 0; o < 14; o++) red[o][tid] = acc[o];
    __syncthreads();
    if (tid < 14) {
        float s = bo[tid];
        for (int k = 0; k < 128; k++) s += red[tid][k];
        out[b * 14 + tid] = sigf(s);
    }
}

// ---------------- launch ----------------
extern "C" void kernel_launch(void* const* d_in, const int* in_sizes, int n_in,
                              void* d_out, int out_size) {
    const float* x    = (const float*)d_in[0];
    const int*   len  = (const int*)  d_in[1];
    const float* h0   = (const float*)d_in[2];
    const float* c0   = (const float*)d_in[3];
    const float* Wis0 = (const float*)d_in[4];
    const float* bis0 = (const float*)d_in[5];
    const float* Wis1 = (const float*)d_in[6];
    const float* bis1 = (const float*)d_in[7];
    const float* Wih  = (const float*)d_in[8];
    const float* Whh  = (const float*)d_in[9];
    const float* bih  = (const float*)d_in[10];
    const float* bhh  = (const float*)d_in[11];
    const float* Wo   = (const float*)d_in[12];
    const float* bo   = (const float*)d_in[13];
    float* out = (float*)d_out;

    cudaFuncSetAttribute(k_rnn,  cudaFuncAttributeMaxDynamicSharedMemorySize, RNN_SMEM);
    cudaFuncSetAttribute(k_gemm, cudaFuncAttributeMaxDynamicSharedMemorySize, GEMM_SMEM);

    k_temb <<<8192, 256>>>(x, len);                              // 1
    k_wtT  <<<8192, 256>>>(Wih);                                 // 2
    k_fold <<<128, 256>>>(Wih, Wis0, bis0, Wis1, bis1, bih, bhh);// 3
    k_gemm <<<dim3(32, 64), 256, GEMM_SMEM>>>(x, len);           // 4  <- profiled slot
    k_sort <<<1, 32>>>(len);                                     // 5
    k_whh2 <<<4096, 256>>>(Whh);                                 // 6
    k_inith<<<256, 256>>>(h0);                                   // 7
    k_rnn  <<<dim3(32, 4), 256, RNN_SMEM>>>(len, c0);            // 8
    k_out  <<<64, 128>>>(Wo, bo, out);                           // 9
}

// round 14
// speedup vs baseline: 1.2651x; 1.0450x over previous
#include <cuda_runtime.h>

#define Hn   512
#define Tn   128
#define Bn   64
#define NROW 128
#define G4   2048
#define KE   1024
#define NTOK 8192

typedef unsigned long long ull;

// ---------------- static device scratch ----------------
__device__ __align__(16) float g_temb[(size_t)NTOK * KE];      // [tok][1024]
// W_ih tail, pre-swizzled: [ptile(32)][kchunk(32)][kp(16)][j(4)][tx(16)] ulls (f32x2 pairs)
__device__ __align__(16) float g_WtT [(size_t)G4 * KE];
__device__ __align__(16) float g_Whh2[(size_t)Hn * G4];        // [jp][u*8 + g*2 + par]
__device__ __align__(16) float g_G   [(size_t)Tn * NROW * G4]; // [t'][orig_r][p]
__device__ __align__(16) float g_Msp [2][8][G4];
__device__ __align__(16) float g_cst [2][G4];
__device__ __align__(16) float g_h   [2][NROW * Hn];           // sorted row order
__device__ __align__(16) float g_hfin[NROW * Hn];              // sorted row order
__device__ int g_sortidx[Bn];   // sorted pos -> orig batch (desc by length)
__device__ int g_inv[Bn];       // orig batch -> sorted pos
__device__ int g_maxlen;
__device__ int          g_ctrg[4];   // per-row-group barrier counters
__device__ volatile int g_relg[4];

// ---------------- helpers ----------------
__device__ __forceinline__ void fma2(ull& d, ull a, ull b) {
    asm("fma.rn.f32x2 %0, %1, %2, %0;" : "+l"(d) : "l"(a), "l"(b));
}
__device__ __forceinline__ float sum2(ull v) {
    float a, b;
    asm("mov.b64 {%0,%1}, %2;" : "=f"(a), "=f"(b) : "l"(v));
    return a + b;
}
__device__ __forceinline__ float sigf(float v) {
    return __fdividef(1.0f, 1.0f + __expf(-v));
}
__device__ __forceinline__ float tanhfast(float v) {
    float e = __expf(2.0f * v);
    return 1.0f - __fdividef(2.0f, e + 1.0f);
}
__device__ __forceinline__ void cpa16(const float* dst_s, const float* src_g) {
    unsigned s = (unsigned)__cvta_generic_to_shared(dst_s);
    asm volatile("cp.async.cg.shared.global [%0], [%1], 16;" :: "r"(s), "l"(src_g));
}
#define CP_COMMIT() asm volatile("cp.async.commit_group;" ::: "memory")
#define CP_WAIT0()  asm volatile("cp.async.wait_group 0;"  ::: "memory")

// ---------------- timestep embeddings (skip dead tokens) ----------------
__global__ void k_temb(const float* __restrict__ x, const int* __restrict__ lengths) {
    int tok = blockIdx.x;
    int b = tok >> 7, t = tok & 127;
    int cl = (__ldg(&lengths[b]) + 1) >> 1;
    if ((t & 63) >= cl) return;          // never consumed by the recurrence
    int k = threadIdx.x;                 // 256
    float t0 = x[tok * 16 + 0], t1 = x[tok * 16 + 1];
    float fr = __expf(-9.210340371976184f * (float)k * (1.0f / 256.0f));
    float s0, c0v, s1, c1v;
    __sincosf(t0 * fr, &s0, &c0v);
    __sincosf(t1 * fr, &s1, &c1v);
    float* o = g_temb + (size_t)tok * KE;
    o[k]       = c0v;
    o[k + 256] = s0;
    o[k + 512] = c1v;
    o[k + 768] = s1;
}

// ---------------- prep: W_ih[:,512:] -> swizzled [ptile][kchunk][kp][j][tx] f32x2 ----------------
__global__ void k_wtT(const float* __restrict__ Wih) {
    int i = blockIdx.x * blockDim.x + threadIdx.x;     // 2097152 exact
    int par    = i & 1;
    int txi    = (i >> 1) & 15;
    int j      = (i >> 5) & 3;
    int kpl    = (i >> 7) & 15;
    int kchunk = (i >> 11) & 31;
    int ptile  = i >> 16;
    int p = ptile * 64 + txi * 4 + j;
    int k = kchunk * 32 + kpl * 2 + par;
    int u = p >> 2, g = p & 3;
    g_WtT[i] = Wih[(size_t)(g * Hn + u) * 1536 + 512 + k];
}

// ---------------- prep: fold segment linears through W_ih ----------------
__global__ void k_fold(const float* __restrict__ Wih,
                       const float* __restrict__ Wis0, const float* __restrict__ bis0,
                       const float* __restrict__ Wis1, const float* __restrict__ bis1,
                       const float* __restrict__ bih,  const float* __restrict__ bhh) {
    int idx = blockIdx.x * blockDim.x + threadIdx.x;   // 32768 = 2048 p * 16 items
    int p = idx >> 4, item = idx & 15;
    int u = p >> 2, g = p & 3;
    const float* wr = Wih + (size_t)(g * Hn + u) * 1536;
    float acc = 0.0f;
    if (item < 8) {
        for (int k = 0; k < Hn; k++) acc += wr[k] * Wis0[k * 8 + item];
        g_Msp[0][item][p] = acc;
    } else if (item < 14) {
        int m = item - 8;
        for (int k = 0; k < Hn; k++) acc += wr[k] * Wis1[k * 6 + m];
        g_Msp[1][m][p] = acc;
    } else if (item == 14) {
        for (int k = 0; k < Hn; k++) acc += wr[k] * bis0[k];
        g_cst[0][p] = acc + bih[g * Hn + u] + bhh[g * Hn + u];
    } else {
        for (int k = 0; k < Hn; k++) acc += wr[k] * bis1[k];
        g_cst[1][p] = acc + bih[g * Hn + u] + bhh[g * Hn + u];
    }
}

// ---------------- big GEMM: alive-prefix row reorder + conflict-free smem + cp.async ----------------
// smem row m holds token t(m) = (m>>1) + ((m&1)<<6)  =>  alive rows are the prefix m < 2*cl.
// A smem: [2][128][18] ulls (f32x2 over k). B smem: [2][16 kp][4 j][16 tx] ulls.
#define AS_ULL (128 * 18)
#define BS_ULL (16 * 4 * 16)
#define GEMM_SMEM ((2 * AS_ULL + 2 * BS_ULL) * 8)

__global__ void __launch_bounds__(256, 2) k_gemm(const float* __restrict__ x,
                                                 const int* __restrict__ lengths) {
    extern __shared__ ull smu[];
    ull* As = smu;                  // [2][128][18]
    ull* Bs = smu + 2 * AS_ULL;     // [2][1024]
    int b     = blockIdx.y;
    int ptile = blockIdx.x;
    int pt    = ptile * 64;
    int tid = threadIdx.x;
    int tx = tid & 15, ty = tid >> 4;
    int m0 = ty * 8, n0 = tx * 4;
    int blen = __ldg(&lengths[b]);
    int mAlive = ((blen + 1) >> 1) * 2;     // alive prefix length (2*cl)
    bool alive = (m0 < mAlive);

    ull acc[8][4];
    #pragma unroll
    for (int i = 0; i < 8; i++)
        #pragma unroll
        for (int j = 0; j < 4; j++) acc[i][j] = 0ull;

    const float* Abase = g_temb + (size_t)b * 128 * KE;
    const float* Bbase = g_WtT + ((size_t)ptile << 16);   // 32 chunks * 2048 floats

    // prologue: chunk 0 -> buffer 0
    {
        float* Ad = (float*)As;
        float* Bd = (float*)Bs;
        #pragma unroll
        for (int it = 0; it < 4; it++) {
            int e = tid + it * 256;                 // 1024 x 16B
            int m = e >> 3, q8 = e & 7;
            if (m < mAlive) {
                int t = (m >> 1) + ((m & 1) << 6);
                cpa16(Ad + (m * 18 + q8 * 2) * 2, Abase + (size_t)t * KE + q8 * 4);
            }
        }
        #pragma unroll
        for (int it = 0; it < 2; it++) {
            int e = tid + it * 256;                 // 512 x 16B
            cpa16(Bd + e * 4, Bbase + e * 4);
        }
        CP_COMMIT();
        CP_WAIT0();
        __syncthreads();
    }

    for (int kc = 0; kc < 32; kc++) {
        int cur = kc & 1, nxt = cur ^ 1;
        if (kc + 1 < 32) {
            float* Ad = (float*)(As + nxt * AS_ULL);
            float* Bd = (float*)(Bs + nxt * BS_ULL);
            int k0n = (kc + 1) * 32;
            #pragma unroll
            for (int it = 0; it < 4; it++) {
                int e = tid + it * 256;
                int m = e >> 3, q8 = e & 7;
                if (m < mAlive) {
                    int t = (m >> 1) + ((m & 1) << 6);
                    cpa16(Ad + (m * 18 + q8 * 2) * 2, Abase + (size_t)t * KE + k0n + q8 * 4);
                }
            }
            #pragma unroll
            for (int it = 0; it < 2; it++) {
                int e = tid + it * 256;
                cpa16(Bd + e * 4, Bbase + (kc + 1) * 2048 + e * 4);
            }
            CP_COMMIT();
        }

        if (alive) {
            const ull* Ab = As + cur * AS_ULL + m0 * 18;
            const ull* Bb = Bs + cur * BS_ULL;
            #pragma unroll
            for (int q = 0; q < 8; q++) {
                ulonglong2 av[8];
                #pragma unroll
                for (int i = 0; i < 8; i++)
                    av[i] = *(const ulonglong2*)(Ab + i * 18 + 2 * q);
                ull b0[4], b1[4];
                #pragma unroll
                for (int j = 0; j < 4; j++) {
                    b0[j] = Bb[(2 * q)     * 64 + j * 16 + tx];
                    b1[j] = Bb[(2 * q + 1) * 64 + j * 16 + tx];
                }
                #pragma unroll
                for (int i = 0; i < 8; i++)
                    #pragma unroll
                    for (int j = 0; j < 4; j++) {
                        fma2(acc[i][j], av[i].x, b0[j]);
                        fma2(acc[i][j], av[i].y, b1[j]);
                    }
            }
        }

        if (kc + 1 < 32) CP_WAIT0();
        __syncthreads();
    }

    // epilogue: add folded segment contribution, route per the concat/reshape quirk
    if (alive) {
        #pragma unroll
        for (int i = 0; i < 8; i++) {
            int m  = m0 + i;
            int tq = m >> 1;                 // t & 63
            int sp = m & 1;                  // scan segment
            int t  = tq + (sp << 6);         // original token row
            const float* xr = x + ((size_t)b * 128 + t) * 16;
            float cval[4];
            #pragma unroll
            for (int j = 0; j < 4; j++) cval[j] = sum2(acc[i][j]);
            #pragma unroll
            for (int se = 0; se < 2; se++) {
                int tp = tq * 2 + se;
                if (tp >= blen) continue;    // never read by the recurrence
                float4 outv;
                float* ov = &outv.x;
                int p = pt + n0;
                #pragma unroll
                for (int j = 0; j < 4; j++) {
                    float v = cval[j] + g_cst[se][p + j];
                    if (se == 0) {
                        #pragma unroll
                        for (int mm = 0; mm < 8; mm++) v += xr[2 + mm] * g_Msp[0][mm][p + j];
                    } else {
                        #pragma unroll
                        for (int mm = 0; mm < 6; mm++) v += xr[10 + mm] * g_Msp[1][mm][p + j];
                    }
                    ov[j] = v;
                }
                *(float4*)&g_G[((size_t)tp * NROW + (b * 2 + sp)) * G4 + p] = outv;
            }
        }
    }
}

// ---------------- sort batches by length (desc), single thread ----------------
__global__ void k_sort(const int* __restrict__ lengths) {
    if (threadIdx.x == 0 && blockIdx.x == 0) {
        int idx[Bn], len[Bn];
        for (int i = 0; i < Bn; i++) { idx[i] = i; len[i] = lengths[i]; }
        for (int a = 0; a < Bn - 1; a++) {
            int m = a;
            for (int b2 = a + 1; b2 < Bn; b2++) if (len[b2] > len[m]) m = b2;
            int tl = len[a]; len[a] = len[m]; len[m] = tl;
            int ti = idx[a]; idx[a] = idx[m]; idx[m] = ti;
        }
        for (int i = 0; i < Bn; i++) { g_sortidx[i] = idx[i]; g_inv[idx[i]] = i; }
        g_maxlen = len[0];
    }
}

// ---------------- prep: permuted W_hh copy ----------------
__global__ void k_whh2(const float* __restrict__ Whh) {
    int i = blockIdx.x * blockDim.x + threadIdx.x;     // 1048576 exact
    int jp = i >> 12, rem = i & 4095;
    int u = rem >> 3, g = (rem >> 1) & 3, par = i & 1;
    g_Whh2[i] = Whh[(size_t)(g * Hn + u) * Hn + 2 * jp + par];
}

// ---------------- init h (sorted row order) + barrier reset ----------------
__global__ void k_inith(const float* __restrict__ h0) {
    int i = blockIdx.x * blockDim.x + threadIdx.x;     // 65536 exact
    int rs = i >> 9, u = i & 511;
    g_h[0][i] = h0[g_sortidx[rs >> 1] * Hn + u];
    if (i < 4) { g_ctrg[i] = 0; g_relg[i] = 0; }
}

// ---------------- persistent recurrence kernel ----------------
// grid (32 unit-tiles, 4 row-groups) = 128 co-resident blocks, 256 threads.
// Each row-group of 32 blocks syncs only among itself and runs only to its own
// groupmax (rows length-sorted desc -> groupmax uniform within the group).
#define HS_STRIDE 516
#define RED_OFF   (32 * HS_STRIDE)
#define RNN_SMEM  ((RED_OFF + 128 * 16) * 4)

__global__ void __launch_bounds__(256, 1) k_rnn(const int* __restrict__ lengths,
                                                const float* __restrict__ c0) {
    extern __shared__ float hs[];            // [32 rows][516] + red[128][16]
    float* red = hs + RED_OFF;
    int tid    = threadIdx.x;
    int uidx   = tid & 15;
    int rslot  = (tid >> 4) & 7;             // 0..7
    int jhalf  = tid >> 7;                   // 0/1
    int unit   = blockIdx.x * 16 + uidx;
    int grp    = blockIdx.y;
    int rowbase = grp * 32;
    int r0 = rowbase + rslot * 4;            // sorted row
    int jp0 = jhalf * 128;

    float c[4];
    int   mylen[4];
    const float* gbase[4];
    #pragma unroll
    for (int i = 0; i < 4; i++) {
        int sr = r0 + i;
        int ob = g_sortidx[sr >> 1];                       // original batch
        c[i]     = __ldg(&c0[ob * Hn + unit]);
        mylen[i] = __ldg(&lengths[ob]);
        gbase[i] = g_G + (size_t)(ob * 2 + (sr & 1)) * G4 + unit * 4;
    }
    int groupmax = __ldg(&lengths[g_sortidx[rowbase >> 1]]);  // uniform in group

    const float* wbase = g_Whh2 + unit * 8;

    for (int t = 0; t < groupmax; t++) {
        const float* hin  = g_h[t & 1];
        float*       hout = g_h[(t + 1) & 1];

        // stage 32-row h tile (4096 float4s); bypass L1
        #pragma unroll
        for (int e = tid; e < 4096; e += 256) {
            int rl = e >> 7, u4 = (e & 127) << 2;
            float4 v = __ldcg((const float4*)(hin + (size_t)(rowbase + rl) * Hn + u4));
            *(float4*)&hs[rl * HS_STRIDE + u4] = v;
        }
        __syncthreads();

        float4 gin[4];
        if (jhalf == 0) {
            #pragma unroll
            for (int i = 0; i < 4; i++)
                gin[i] = __ldcg((const float4*)(gbase[i] + (size_t)t * NROW * G4));
        }

        ull acc[4][4];
        #pragma unroll
        for (int i = 0; i < 4; i++)
            #pragma unroll
            for (int g = 0; g < 4; g++) acc[i][g] = 0ull;

        const float* hp = hs + (size_t)(rslot * 4) * HS_STRIDE;
        #pragma unroll 4
        for (int jp = jp0; jp < jp0 + 128; jp++) {
            ulonglong2 wA = *(const ulonglong2*)(wbase + (size_t)jp * 4096);
            ulonglong2 wB = *(const ulonglong2*)(wbase + (size_t)jp * 4096 + 4);
            ull h0 = *(const ull*)(hp + 0 * HS_STRIDE + jp * 2);
            ull h1 = *(const ull*)(hp + 1 * HS_STRIDE + jp * 2);
            ull h2 = *(const ull*)(hp + 2 * HS_STRIDE + jp * 2);
            ull h3 = *(const ull*)(hp + 3 * HS_STRIDE + jp * 2);
            fma2(acc[0][0], h0, wA.x); fma2(acc[0][1], h0, wA.y);
            fma2(acc[0][2], h0, wB.x); fma2(acc[0][3], h0, wB.y);
            fma2(acc[1][0], h1, wA.x); fma2(acc[1][1], h1, wA.y);
            fma2(acc[1][2], h1, wB.x); fma2(acc[1][3], h1, wB.y);
            fma2(acc[2][0], h2, wA.x); fma2(acc[2][1], h2, wA.y);
            fma2(acc[2][2], h2, wB.x); fma2(acc[2][3], h2, wB.y);
            fma2(acc[3][0], h3, wA.x); fma2(acc[3][1], h3, wA.y);
            fma2(acc[3][2], h3, wB.x); fma2(acc[3][3], h3, wB.y);
        }

        if (jhalf == 1) {
            float* rp = red + (rslot * 16 + uidx) * 16;
            #pragma unroll
            for (int i = 0; i < 4; i++)
                #pragma unroll
                for (int g = 0; g < 4; g++) rp[i * 4 + g] = sum2(acc[i][g]);
        }
        __syncthreads();

        if (jhalf == 0) {
            const float* rp = red + (rslot * 16 + uidx) * 16;
            #pragma unroll
            for (int i = 0; i < 4; i++) {
                int r = r0 + i;
                float iv = sum2(acc[i][0]) + rp[i * 4 + 0] + gin[i].x;
                float fv = sum2(acc[i][1]) + rp[i * 4 + 1] + gin[i].y;
                float gv = sum2(acc[i][2]) + rp[i * 4 + 2] + gin[i].z;
                float ov = sum2(acc[i][3]) + rp[i * 4 + 3] + gin[i].w;
                float ig = sigf(iv), fg = sigf(fv), og = sigf(ov);
                float gg = tanhfast(gv);
                c[i] = fg * c[i] + ig * gg;
                float h = og * tanhfast(c[i]);
                __stcg(&hout[(size_t)r * Hn + unit], h);
                if (t + 1 == mylen[i]) g_hfin[(size_t)r * Hn + unit] = h;
            }
        }
        __syncthreads();

        // per-group barrier (32 co-resident blocks; monotonic counter)
        if (tid == 0) {
            __threadfence();
            int old = atomicAdd(&g_ctrg[grp], 1);
            if (old == (t + 1) * 32 - 1) {
                g_relg[grp] = t + 1;
            } else {
                while (g_relg[grp] < t + 1) { }
            }
        }
        __syncthreads();
    }
}

// ---------------- output head ----------------
__global__ void k_out(const float* __restrict__ Wo, const float* __restrict__ bo,
                      float* __restrict__ out) {
    __shared__ float red[14][129];
    int b = blockIdx.x, tid = threadIdx.x;   // 128 threads
    int pos = g_inv[b];
    float acc[14];
    #pragma unroll
    for (int o = 0; o < 14; o++) acc[o] = 0.0f;
    for (int q = tid; q < 1024; q += 128) {
        int row = pos * 2 + (q >> 9);
        float hv = g_hfin[row * Hn + (q & 511)];
        #pragma unroll
        for (int o = 0; o < 14; o++) acc[o] += hv * Wo[o * 1024 + q];
    }
    #pragma unroll
    for (int o = 0; o < 14; o++) red[o][tid] = acc[o];
    __syncthreads();
    if (tid < 14) {
        float s = bo[tid];
        for (int k = 0; k < 128; k++) s += red[tid][k];
        out[b * 14 + tid] = sigf(s);
    }
}

// ---------------- launch ----------------
extern "C" void kernel_launch(void* const* d_in, const int* in_sizes, int n_in,
                              void* d_out, int out_size) {
    const float* x    = (const float*)d_in[0];
    const int*   len  = (const int*)  d_in[1];
    const float* h0   = (const float*)d_in[2];
    const float* c0   = (const float*)d_in[3];
    const float* Wis0 = (const float*)d_in[4];
    const float* bis0 = (const float*)d_in[5];
    const float* Wis1 = (const float*)d_in[6];
    const float* bis1 = (const float*)d_in[7];
    const float* Wih  = (const float*)d_in[8];
    const float* Whh  = (const float*)d_in[9];
    const float* bih  = (const float*)d_in[10];
    const float* bhh  = (const float*)d_in[11];
    const float* Wo   = (const float*)d_in[12];
    const float* bo   = (const float*)d_in[13];
    float* out = (float*)d_out;

    cudaFuncSetAttribute(k_rnn,  cudaFuncAttributeMaxDynamicSharedMemorySize, RNN_SMEM);
    cudaFuncSetAttribute(k_gemm, cudaFuncAttributeMaxDynamicSharedMemorySize, GEMM_SMEM);

    k_temb <<<8192, 256>>>(x, len);                              // 1
    k_wtT  <<<8192, 256>>>(Wih);                                 // 2
    k_fold <<<128, 256>>>(Wih, Wis0, bis0, Wis1, bis1, bih, bhh);// 3
    k_gemm <<<dim3(32, 64), 256, GEMM_SMEM>>>(x, len);           // 4  <- profiled slot
    k_sort <<<1, 32>>>(len);                                     // 5
    k_whh2 <<<4096, 256>>>(Whh);                                 // 6
    k_inith<<<256, 256>>>(h0);                                   // 7
    k_rnn  <<<dim3(32, 4), 256, RNN_SMEM>>>(len, c0);            // 8
    k_out  <<<64, 128>>>(Wo, bo, out);                           // 9
}

// round 17
// speedup vs baseline: 1.4648x; 1.1579x over previous
#include <cuda_runtime.h>

#define Hn   512
#define Tn   128
#define Bn   64
#define NROW 128
#define G4   2048
#define KE   1024
#define NTOK 8192

typedef unsigned long long ull;

// ---------------- static device scratch ----------------
__device__ __align__(16) float g_temb[(size_t)NTOK * KE];      // [tok][1024]
// W_ih tail, pre-swizzled: [ptile(32)][kchunk(32)][kp(16)][j(4)][tx(16)] ulls (f32x2 pairs)
__device__ __align__(16) float g_WtT [(size_t)G4 * KE];
__device__ __align__(16) float g_Whh2[(size_t)Hn * G4];        // [jp][u*8 + g*2 + par]
__device__ __align__(16) float g_G   [(size_t)Tn * NROW * G4]; // [t'][orig_r][p]
__device__ __align__(16) float g_Msp [2][8][G4];
__device__ __align__(16) float g_cst [2][G4];
__device__ __align__(16) float g_h   [2][NROW * Hn];           // sorted row order
__device__ __align__(16) float g_hfin[NROW * Hn];              // sorted row order
__device__ int g_sortidx[Bn];   // sorted pos -> orig batch (desc by length)
__device__ int g_inv[Bn];       // orig batch -> sorted pos
__device__ int g_maxlen;
__device__ int          g_ctrg[4];   // per-row-group barrier counters
__device__ volatile int g_relg[4];

// ---------------- helpers ----------------
__device__ __forceinline__ void fma2(ull& d, ull a, ull b) {
    asm("fma.rn.f32x2 %0, %1, %2, %0;" : "+l"(d) : "l"(a), "l"(b));
}
__device__ __forceinline__ float sum2(ull v) {
    float a, b;
    asm("mov.b64 {%0,%1}, %2;" : "=f"(a), "=f"(b) : "l"(v));
    return a + b;
}
__device__ __forceinline__ float sigf(float v) {
    return __fdividef(1.0f, 1.0f + __expf(-v));
}
__device__ __forceinline__ float tanhfast(float v) {
    float e = __expf(2.0f * v);
    return 1.0f - __fdividef(2.0f, e + 1.0f);
}
__device__ __forceinline__ void cpa16(const float* dst_s, const float* src_g) {
    unsigned s = (unsigned)__cvta_generic_to_shared(dst_s);
    asm volatile("cp.async.cg.shared.global [%0], [%1], 16;" :: "r"(s), "l"(src_g));
}
#define CP_COMMIT() asm volatile("cp.async.commit_group;" ::: "memory")
#define CP_WAIT0()  asm volatile("cp.async.wait_group 0;"  ::: "memory")

// ---------------- timestep embeddings (skip dead tokens) ----------------
__global__ void k_temb(const float* __restrict__ x, const int* __restrict__ lengths) {
    int tok = blockIdx.x;
    int b = tok >> 7, t = tok & 127;
    int cl = (__ldg(&lengths[b]) + 1) >> 1;
    if ((t & 63) >= cl) return;          // never consumed by the recurrence
    int k = threadIdx.x;                 // 256
    float t0 = x[tok * 16 + 0], t1 = x[tok * 16 + 1];
    float fr = __expf(-9.210340371976184f * (float)k * (1.0f / 256.0f));
    float s0, c0v, s1, c1v;
    __sincosf(t0 * fr, &s0, &c0v);
    __sincosf(t1 * fr, &s1, &c1v);
    float* o = g_temb + (size_t)tok * KE;
    o[k]       = c0v;
    o[k + 256] = s0;
    o[k + 512] = c1v;
    o[k + 768] = s1;
}

// ---------------- prep: W_ih[:,512:] -> swizzled [ptile][kchunk][kp][j][tx] f32x2 ----------------
__global__ void k_wtT(const float* __restrict__ Wih) {
    int i = blockIdx.x * blockDim.x + threadIdx.x;     // 2097152 exact
    int par    = i & 1;
    int txi    = (i >> 1) & 15;
    int j      = (i >> 5) & 3;
    int kpl    = (i >> 7) & 15;
    int kchunk = (i >> 11) & 31;
    int ptile  = i >> 16;
    int p = ptile * 64 + txi * 4 + j;
    int k = kchunk * 32 + kpl * 2 + par;
    int u = p >> 2, g = p & 3;
    g_WtT[i] = Wih[(size_t)(g * Hn + u) * 1536 + 512 + k];
}

// ---------------- prep: fold segment linears through W_ih ----------------
__global__ void k_fold(const float* __restrict__ Wih,
                       const float* __restrict__ Wis0, const float* __restrict__ bis0,
                       const float* __restrict__ Wis1, const float* __restrict__ bis1,
                       const float* __restrict__ bih,  const float* __restrict__ bhh) {
    int idx = blockIdx.x * blockDim.x + threadIdx.x;   // 32768 = 2048 p * 16 items
    int p = idx >> 4, item = idx & 15;
    int u = p >> 2, g = p & 3;
    const float* wr = Wih + (size_t)(g * Hn + u) * 1536;
    float acc = 0.0f;
    if (item < 8) {
        for (int k = 0; k < Hn; k++) acc += wr[k] * Wis0[k * 8 + item];
        g_Msp[0][item][p] = acc;
    } else if (item < 14) {
        int m = item - 8;
        for (int k = 0; k < Hn; k++) acc += wr[k] * Wis1[k * 6 + m];
        g_Msp[1][m][p] = acc;
    } else if (item == 14) {
        for (int k = 0; k < Hn; k++) acc += wr[k] * bis0[k];
        g_cst[0][p] = acc + bih[g * Hn + u] + bhh[g * Hn + u];
    } else {
        for (int k = 0; k < Hn; k++) acc += wr[k] * bis1[k];
        g_cst[1][p] = acc + bih[g * Hn + u] + bhh[g * Hn + u];
    }
}

// ---------------- big GEMM: alive-prefix row reorder + conflict-free smem + cp.async ----------------
#define AS_ULL (128 * 18)
#define BS_ULL (16 * 4 * 16)
#define GEMM_SMEM ((2 * AS_ULL + 2 * BS_ULL) * 8)

__global__ void __launch_bounds__(256, 2) k_gemm(const float* __restrict__ x,
                                                 const int* __restrict__ lengths) {
    extern __shared__ ull smu[];
    ull* As = smu;                  // [2][128][18]
    ull* Bs = smu + 2 * AS_ULL;     // [2][1024]
    int b     = blockIdx.y;
    int ptile = blockIdx.x;
    int pt    = ptile * 64;
    int tid = threadIdx.x;
    int tx = tid & 15, ty = tid >> 4;
    int m0 = ty * 8, n0 = tx * 4;
    int blen = __ldg(&lengths[b]);
    int mAlive = ((blen + 1) >> 1) * 2;     // alive prefix length (2*cl)
    bool alive = (m0 < mAlive);

    ull acc[8][4];
    #pragma unroll
    for (int i = 0; i < 8; i++)
        #pragma unroll
        for (int j = 0; j < 4; j++) acc[i][j] = 0ull;

    const float* Abase = g_temb + (size_t)b * 128 * KE;
    const float* Bbase = g_WtT + ((size_t)ptile << 16);   // 32 chunks * 2048 floats

    // prologue: chunk 0 -> buffer 0
    {
        float* Ad = (float*)As;
        float* Bd = (float*)Bs;
        #pragma unroll
        for (int it = 0; it < 4; it++) {
            int e = tid + it * 256;                 // 1024 x 16B
            int m = e >> 3, q8 = e & 7;
            if (m < mAlive) {
                int t = (m >> 1) + ((m & 1) << 6);
                cpa16(Ad + (m * 18 + q8 * 2) * 2, Abase + (size_t)t * KE + q8 * 4);
            }
        }
        #pragma unroll
        for (int it = 0; it < 2; it++) {
            int e = tid + it * 256;                 // 512 x 16B
            cpa16(Bd + e * 4, Bbase + e * 4);
        }
        CP_COMMIT();
        CP_WAIT0();
        __syncthreads();
    }

    for (int kc = 0; kc < 32; kc++) {
        int cur = kc & 1, nxt = cur ^ 1;
        if (kc + 1 < 32) {
            float* Ad = (float*)(As + nxt * AS_ULL);
            float* Bd = (float*)(Bs + nxt * BS_ULL);
            int k0n = (kc + 1) * 32;
            #pragma unroll
            for (int it = 0; it < 4; it++) {
                int e = tid + it * 256;
                int m = e >> 3, q8 = e & 7;
                if (m < mAlive) {
                    int t = (m >> 1) + ((m & 1) << 6);
                    cpa16(Ad + (m * 18 + q8 * 2) * 2, Abase + (size_t)t * KE + k0n + q8 * 4);
                }
            }
            #pragma unroll
            for (int it = 0; it < 2; it++) {
                int e = tid + it * 256;
                cpa16(Bd + e * 4, Bbase + (kc + 1) * 2048 + e * 4);
            }
            CP_COMMIT();
        }

        if (alive) {
            const ull* Ab = As + cur * AS_ULL + m0 * 18;
            const ull* Bb = Bs + cur * BS_ULL;
            #pragma unroll
            for (int q = 0; q < 8; q++) {
                ulonglong2 av[8];
                #pragma unroll
                for (int i = 0; i < 8; i++)
                    av[i] = *(const ulonglong2*)(Ab + i * 18 + 2 * q);
                ull b0[4], b1[4];
                #pragma unroll
                for (int j = 0; j < 4; j++) {
                    b0[j] = Bb[(2 * q)     * 64 + j * 16 + tx];
                    b1[j] = Bb[(2 * q + 1) * 64 + j * 16 + tx];
                }
                #pragma unroll
                for (int i = 0; i < 8; i++)
                    #pragma unroll
                    for (int j = 0; j < 4; j++) {
                        fma2(acc[i][j], av[i].x, b0[j]);
                        fma2(acc[i][j], av[i].y, b1[j]);
                    }
            }
        }

        if (kc + 1 < 32) CP_WAIT0();
        __syncthreads();
    }

    // epilogue: add folded segment contribution, route per the concat/reshape quirk
    if (alive) {
        #pragma unroll
        for (int i = 0; i < 8; i++) {
            int m  = m0 + i;
            int tq = m >> 1;                 // t & 63
            int sp = m & 1;                  // scan segment
            int t  = tq + (sp << 6);         // original token row
            const float* xr = x + ((size_t)b * 128 + t) * 16;
            float cval[4];
            #pragma unroll
            for (int j = 0; j < 4; j++) cval[j] = sum2(acc[i][j]);
            #pragma unroll
            for (int se = 0; se < 2; se++) {
                int tp = tq * 2 + se;
                if (tp >= blen) continue;    // never read by the recurrence
                float4 outv;
                float* ov = &outv.x;
                int p = pt + n0;
                #pragma unroll
                for (int j = 0; j < 4; j++) {
                    float v = cval[j] + g_cst[se][p + j];
                    if (se == 0) {
                        #pragma unroll
                        for (int mm = 0; mm < 8; mm++) v += xr[2 + mm] * g_Msp[0][mm][p + j];
                    } else {
                        #pragma unroll
                        for (int mm = 0; mm < 6; mm++) v += xr[10 + mm] * g_Msp[1][mm][p + j];
                    }
                    ov[j] = v;
                }
                *(float4*)&g_G[((size_t)tp * NROW + (b * 2 + sp)) * G4 + p] = outv;
            }
        }
    }
}

// ---------------- sort batches by length (desc), single thread ----------------
__global__ void k_sort(const int* __restrict__ lengths) {
    if (threadIdx.x == 0 && blockIdx.x == 0) {
        int idx[Bn], len[Bn];
        for (int i = 0; i < Bn; i++) { idx[i] = i; len[i] = lengths[i]; }
        for (int a = 0; a < Bn - 1; a++) {
            int m = a;
            for (int b2 = a + 1; b2 < Bn; b2++) if (len[b2] > len[m]) m = b2;
            int tl = len[a]; len[a] = len[m]; len[m] = tl;
            int ti = idx[a]; idx[a] = idx[m]; idx[m] = ti;
        }
        for (int i = 0; i < Bn; i++) { g_sortidx[i] = idx[i]; g_inv[idx[i]] = i; }
        g_maxlen = len[0];
    }
}

// ---------------- prep: permuted W_hh copy ----------------
__global__ void k_whh2(const float* __restrict__ Whh) {
    int i = blockIdx.x * blockDim.x + threadIdx.x;     // 1048576 exact
    int jp = i >> 12, rem = i & 4095;
    int u = rem >> 3, g = (rem >> 1) & 3, par = i & 1;
    g_Whh2[i] = Whh[(size_t)(g * Hn + u) * Hn + 2 * jp + par];
}

// ---------------- init h (sorted row order) + barrier reset ----------------
__global__ void k_inith(const float* __restrict__ h0) {
    int i = blockIdx.x * blockDim.x + threadIdx.x;     // 65536 exact
    int rs = i >> 9, u = i & 511;
    g_h[0][i] = h0[g_sortidx[rs >> 1] * Hn + u];
    if (i < 4) { g_ctrg[i] = 0; g_relg[i] = 0; }
}

// ---------------- persistent recurrence kernel ----------------
// grid (32 unit-tiles, 4 row-groups) = 128 co-resident blocks, 256 threads.
// thread = 8 rows x 1 unit x quarter-K: uidx(16) x rslot(4, 8 rows each) x jq(4).
// 8 rows/thread amortizes the W LDG.128s over 2x more fma2; h reads are
// 2-address LDS.128 broadcasts. NOTE: hs is indexed by LOCAL row (rslot*8).
#define HS_STRIDE 516
#define RED_OFF   (32 * HS_STRIDE)
#define RED_ELT   (64 * 100)
#define RNN_SMEM  ((RED_OFF + RED_ELT) * 4)

__global__ void __launch_bounds__(256, 1) k_rnn(const int* __restrict__ lengths,
                                                const float* __restrict__ c0) {
    extern __shared__ float hs[];            // h [32][516] + red [64][100]
    float* red = hs + RED_OFF;
    int tid   = threadIdx.x;
    int uidx  = tid & 15;
    int rslot = (tid >> 4) & 3;              // 0..3, 8 rows each
    int jq    = tid >> 6;                    // 0..3, 64 jp each
    int unit  = blockIdx.x * 16 + uidx;
    int grp   = blockIdx.y;
    int rowbase = grp * 32;
    int r0 = rowbase + rslot * 8;            // sorted (global) row
    int jp0 = jq * 64;

    float c[8];
    int   mylen[8];
    const float* gbase[8];
    #pragma unroll
    for (int i = 0; i < 8; i++) {
        int sr = r0 + i;
        int ob = g_sortidx[sr >> 1];                       // original batch
        c[i]     = __ldg(&c0[ob * Hn + unit]);
        mylen[i] = __ldg(&lengths[ob]);
        gbase[i] = g_G + (size_t)(ob * 2 + (sr & 1)) * G4 + unit * 4;
    }
    int groupmax = __ldg(&lengths[g_sortidx[rowbase >> 1]]);  // uniform in group

    const float* wbase = g_Whh2 + unit * 8;

    for (int t = 0; t < groupmax; t++) {
        const float* hin  = g_h[t & 1];
        float*       hout = g_h[(t + 1) & 1];

        // stage 32-row h tile (4096 float4s); bypass L1
        #pragma unroll
        for (int e = tid; e < 4096; e += 256) {
            int rl = e >> 7, u4 = (e & 127) << 2;
            float4 v = __ldcg((const float4*)(hin + (size_t)(rowbase + rl) * Hn + u4));
            *(float4*)&hs[rl * HS_STRIDE + u4] = v;
        }
        __syncthreads();

        float4 gin[8];
        if (jq == 0) {
            #pragma unroll
            for (int i = 0; i < 8; i++)
                gin[i] = __ldcg((const float4*)(gbase[i] + (size_t)t * NROW * G4));
        }

        ull acc[8][4];
        #pragma unroll
        for (int i = 0; i < 8; i++)
            #pragma unroll
            for (int g = 0; g < 4; g++) acc[i][g] = 0ull;

        const float* hpb = hs + (size_t)(rslot * 8) * HS_STRIDE;   // LOCAL row base
        #pragma unroll 2
        for (int jp = jp0; jp < jp0 + 64; jp += 2) {
            ulonglong2 wA0 = *(const ulonglong2*)(wbase + (size_t)jp * 4096);
            ulonglong2 wB0 = *(const ulonglong2*)(wbase + (size_t)jp * 4096 + 4);
            ulonglong2 wA1 = *(const ulonglong2*)(wbase + (size_t)(jp + 1) * 4096);
            ulonglong2 wB1 = *(const ulonglong2*)(wbase + (size_t)(jp + 1) * 4096 + 4);
            #pragma unroll
            for (int i = 0; i < 8; i++) {
                ulonglong2 hv = *(const ulonglong2*)(hpb + (size_t)i * HS_STRIDE + jp * 2);
                fma2(acc[i][0], hv.x, wA0.x); fma2(acc[i][1], hv.x, wA0.y);
                fma2(acc[i][2], hv.x, wB0.x); fma2(acc[i][3], hv.x, wB0.y);
                fma2(acc[i][0], hv.y, wA1.x); fma2(acc[i][1], hv.y, wA1.y);
                fma2(acc[i][2], hv.y, wB1.x); fma2(acc[i][3], hv.y, wB1.y);
            }
        }

        // combine the four K-quarters: jq>0 write partials, jq0 adds + epilogue
        if (jq != 0) {
            float* rp = red + (rslot * 16 + uidx) * 100 + (jq - 1) * 32;
            #pragma unroll
            for (int i = 0; i < 8; i++)
                #pragma unroll
                for (int g = 0; g < 4; g++) rp[i * 4 + g] = sum2(acc[i][g]);
        }
        __syncthreads();

        if (jq == 0) {
            const float* rp = red + (rslot * 16 + uidx) * 100;
            #pragma unroll
            for (int i = 0; i < 8; i++) {
                int r = r0 + i;
                float iv = sum2(acc[i][0]) + rp[i*4+0] + rp[32+i*4+0] + rp[64+i*4+0] + gin[i].x;
                float fv = sum2(acc[i][1]) + rp[i*4+1] + rp[32+i*4+1] + rp[64+i*4+1] + gin[i].y;
                float gv = sum2(acc[i][2]) + rp[i*4+2] + rp[32+i*4+2] + rp[64+i*4+2] + gin[i].z;
                float ov = sum2(acc[i][3]) + rp[i*4+3] + rp[32+i*4+3] + rp[64+i*4+3] + gin[i].w;
                float ig = sigf(iv), fg = sigf(fv), og = sigf(ov);
                float gg = tanhfast(gv);
                c[i] = fg * c[i] + ig * gg;
                float h = og * tanhfast(c[i]);
                __stcg(&hout[(size_t)r * Hn + unit], h);
                if (t + 1 == mylen[i]) g_hfin[(size_t)r * Hn + unit] = h;
            }
        }
        __syncthreads();

        // per-group barrier (32 co-resident blocks; monotonic counter)
        if (tid == 0) {
            __threadfence();
            int old = atomicAdd(&g_ctrg[grp], 1);
            if (old == (t + 1) * 32 - 1) {
                g_relg[grp] = t + 1;
            } else {
                while (g_relg[grp] < t + 1) { }
            }
        }
        __syncthreads();
    }
}

// ---------------- output head ----------------
__global__ void k_out(const float* __restrict__ Wo, const float* __restrict__ bo,
                      float* __restrict__ out) {
    __shared__ float red[14][129];
    int b = blockIdx.x, tid = threadIdx.x;   // 128 threads
    int pos = g_inv[b];
    float acc[14];
    #pragma unroll
    for (int o = 0; o < 14; o++) acc[o] = 0.0f;
    for (int q = tid; q < 1024; q += 128) {
        int row = pos * 2 + (q >> 9);
        float hv = g_hfin[row * Hn + (q & 511)];
        #pragma unroll
        for (int o = 0; o < 14; o++) acc[o] += hv * Wo[o * 1024 + q];
    }
    #pragma unroll
    for (int o = 0; o < 14; o++) red[o][tid] = acc[o];
    __syncthreads();
    if (tid < 14) {
        float s = bo[tid];
        for (int k = 0; k < 128; k++) s += red[tid][k];
        out[b * 14 + tid] = sigf(s);
    }
}

// ---------------- launch ----------------
extern "C" void kernel_launch(void* const* d_in, const int* in_sizes, int n_in,
                              void* d_out, int out_size) {
    const float* x    = (const float*)d_in[0];
    const int*   len  = (const int*)  d_in[1];
    const float* h0   = (const float*)d_in[2];
    const float* c0   = (const float*)d_in[3];
    const float* Wis0 = (const float*)d_in[4];
    const float* bis0 = (const float*)d_in[5];
    const float* Wis1 = (const float*)d_in[6];
    const float* bis1 = (const float*)d_in[7];
    const float* Wih  = (const float*)d_in[8];
    const float* Whh  = (const float*)d_in[9];
    const float* bih  = (const float*)d_in[10];
    const float* bhh  = (const float*)d_in[11];
    const float* Wo   = (const float*)d_in[12];
    const float* bo   = (const float*)d_in[13];
    float* out = (float*)d_out;

    cudaFuncSetAttribute(k_rnn,  cudaFuncAttributeMaxDynamicSharedMemorySize, RNN_SMEM);
    cudaFuncSetAttribute(k_gemm, cudaFuncAttributeMaxDynamicSharedMemorySize, GEMM_SMEM);

    k_temb <<<8192, 256>>>(x, len);                              // 1
    k_wtT  <<<8192, 256>>>(Wih);                                 // 2
    k_fold <<<128, 256>>>(Wih, Wis0, bis0, Wis1, bis1, bih, bhh);// 3
    k_gemm <<<dim3(32, 64), 256, GEMM_SMEM>>>(x, len);           // 4  <- profiled slot
    k_sort <<<1, 32>>>(len);                                     // 5
    k_whh2 <<<4096, 256>>>(Whh);                                 // 6
    k_inith<<<256, 256>>>(h0);                                   // 7
    k_rnn  <<<dim3(32, 4), 256, RNN_SMEM>>>(len, c0);            // 8
    k_out  <<<64, 128>>>(Wo, bo, out);                           // 9
}